// round 6
// baseline (speedup 1.0000x reference)
#include <cuda_runtime.h>

#define TPB  256
#define PPT  4
#define TILE (TPB * PPT)   // 1024 points per block

// Cell record: 5 float4s per cell
//  v0: ax, ay, bx, by
//  v1: cx, cy, d0x(=bx-ax), d0y(=by-ay)
//  v2: d1x(=cx-bx), d1y(=cy-by), d2x(=ax-cx), d2y(=ay-cy)
//  v3: ocx, ocy, r2, ecx
//  v4: ecy, 1/erx, 1/ery, pad

// Shade one cell, update best. Exact reference op order (no fma contraction).
#define SHADE_CELL(cc)                                                         \
    do {                                                                       \
        int _c = (cc);                                                         \
        float4 v0 = rec[_c * 5 + 0];                                           \
        float4 v1 = rec[_c * 5 + 1];                                           \
        float4 v2 = rec[_c * 5 + 2];                                           \
        float4 v3 = rec[_c * 5 + 3];                                           \
        float4 v4 = rec[_c * 5 + 4];                                           \
        float e0 = __fsub_rn(__fmul_rn(__fsub_rn(px, v0.x), v1.w),             \
                             __fmul_rn(__fsub_rn(py, v0.y), v1.z));            \
        float e1 = __fsub_rn(__fmul_rn(__fsub_rn(px, v0.z), v2.y),             \
                             __fmul_rn(__fsub_rn(py, v0.w), v2.x));            \
        float e2 = __fsub_rn(__fmul_rn(__fsub_rn(px, v1.x), v2.w),             \
                             __fmul_rn(__fsub_rn(py, v1.y), v2.z));            \
        float emin = fminf(fminf(e0, e1), e2);                                 \
        float emax = fmaxf(fmaxf(e0, e1), e2);                                 \
        bool tri_in = (emin >= 0.0f) || (emax <= 0.0f);                        \
        float dxc = __fsub_rn(px, v3.x), dyc = __fsub_rn(py, v3.y);            \
        bool circ_in =                                                         \
            __fadd_rn(__fmul_rn(dxc, dxc), __fmul_rn(dyc, dyc)) <= v3.z;       \
        float xn = __fmul_rn(__fsub_rn(px, v3.w), v4.y);                       \
        float yn = __fmul_rn(__fsub_rn(py, v4.x), v4.z);                       \
        bool ell_in =                                                          \
            __fadd_rn(__fmul_rn(xn, xn), __fmul_rn(yn, yn)) <= 1.0f;           \
        int c3 = _c * 3;                                                       \
        int cb = tri_in ? c3 : -1;                                             \
        cb = circ_in ? c3 + 1 : cb;                                            \
        cb = ell_in ? c3 + 2 : cb;                                             \
        best = best > cb ? best : cb;                                          \
    } while (0)

__global__ __launch_bounds__(TPB)
void vg_kernel(const float* __restrict__ x, const float* __restrict__ p,
               float* __restrict__ out, int n)
{
    __shared__ float4 rec[25 * 5];
    __shared__ float  colors[76 * 3];      // slot 0 = black
    __shared__ float2 sp[TILE];            // (cell,quadrant)-sorted points
    __shared__ unsigned int sinfo[TILE];   // orig | cc<<10 | (dx+1)<<15 | (dy+1)<<17 | vx<<19 | vy<<20
    __shared__ unsigned char sbest[TILE];  // winner+1 per ORIGINAL point
    __shared__ int hist[225];
    __shared__ int off[225];
    __shared__ int wsum[8];

    const int tid = threadIdx.x;

    if (tid < 25) {
        const float* q = p + tid * 28;
        float ax = q[1], ay = q[2], bx = q[3], by = q[4], cx = q[5], cy = q[6];
        rec[tid * 5 + 0] = make_float4(ax, ay, bx, by);
        rec[tid * 5 + 1] = make_float4(cx, cy, __fsub_rn(bx, ax), __fsub_rn(by, ay));
        rec[tid * 5 + 2] = make_float4(__fsub_rn(cx, bx), __fsub_rn(cy, by),
                                       __fsub_rn(ax, cx), __fsub_rn(ay, cy));
        float ocx = q[12], ocy = q[13], r = q[14];
        float ecx = q[20], ecy = q[21], erx = q[22], ery = q[23];
        rec[tid * 5 + 3] = make_float4(ocx, ocy, __fmul_rn(r, r), ecx);
        rec[tid * 5 + 4] = make_float4(ecy, 1.0f / erx, 1.0f / ery, 0.0f);
    }
    for (int idx = tid; idx < 228; idx += TPB) {
        if (idx < 3) colors[idx] = 0.0f;
        else {
            int s = (idx - 3) / 3, k = (idx - 3) % 3;
            int c = s / 3, t = s % 3;
            int o = (t == 0) ? (8 + k) : ((t == 1) ? (16 + k) : (25 + k));
            colors[idx] = p[c * 28 + o];
        }
    }
    if (tid < 225) hist[tid] = 0;
    __syncthreads();

    const int base = blockIdx.x * TILE;

    // ---- Phase 1: load points, classify, histogram (all state in regs) ----
    float2   pts[PPT];
    int      keyr[PPT];
    int      rankr[PPT];
    unsigned infor[PPT];
#pragma unroll
    for (int k = 0; k < PPT; k++) {
        int li = k * TPB + tid;
        int gi = base + li;
        float2 pt = (gi < n) ? ((const float2*)x)[gi] : make_float2(0.5f, 0.5f);
        pts[k] = pt;
        float gx = pt.x * 5.0f, gy = pt.y * 5.0f;
        int ci = (int)gx; ci = ci > 4 ? 4 : (ci < 0 ? 0 : ci);
        int cj = (int)gy; cj = cj > 4 ? 4 : (cj < 0 ? 0 : cj);
        float fx = gx - (float)ci;
        float fy = gy - (float)cj;
        // shapes extend at most 0.4 cell-widths outside their cell;
        // 0.41/0.59 thresholds leave a 0.002-abs margin >> f32 rounding
        int dxn = (fx <= 0.41f) ? -1 : ((fx >= 0.59f) ? 1 : 0);
        int dyn = (fy <= 0.41f) ? -1 : ((fy >= 0.59f) ? 1 : 0);
        int i2 = ci + dxn, j2 = cj + dyn;
        unsigned vx = (dxn != 0) && ((unsigned)i2 <= 4u);
        unsigned vy = (dyn != 0) && ((unsigned)j2 <= 4u);
        int cc = ci * 5 + cj;
        int key = cc * 9 + (dxn + 1) * 3 + (dyn + 1);
        keyr[k]  = key;
        rankr[k] = atomicAdd(&hist[key], 1);
        infor[k] = (unsigned)li | ((unsigned)cc << 10) |
                   ((unsigned)(dxn + 1) << 15) | ((unsigned)(dyn + 1) << 17) |
                   (vx << 19) | (vy << 20);
    }
    __syncthreads();

    // ---- Phase 2: exclusive scan of 225 bins (two-level shuffle scan) ----
    {
        int v = (tid < 225) ? hist[tid] : 0;
        int s = v;
#pragma unroll
        for (int d = 1; d < 32; d <<= 1) {
            int t = __shfl_up_sync(0xffffffff, s, d);
            if ((tid & 31) >= d) s += t;
        }
        if ((tid & 31) == 31) wsum[tid >> 5] = s;
        __syncthreads();
        if (tid < 8) {
            int w = wsum[tid];
            int sw = w;
#pragma unroll
            for (int d = 1; d < 8; d <<= 1) {
                int t = __shfl_up_sync(0xff, sw, d);
                if (tid >= d) sw += t;
            }
            wsum[tid] = sw - w;
        }
        __syncthreads();
        if (tid < 225) off[tid] = (s - v) + wsum[tid >> 5];
    }
    __syncthreads();

    // ---- Phase 3: scatter into sorted order ----
#pragma unroll
    for (int k = 0; k < PPT; k++) {
        int pos = off[keyr[k]] + rankr[k];
        sp[pos]    = pts[k];
        sinfo[pos] = infor[k];
    }
    __syncthreads();

    // ---- Phase 4: shade sorted points (warp-uniform cells + branches) ----
#pragma unroll 1
    for (int k = 0; k < PPT; k++) {
        int li = k * TPB + tid;
        float2 pt = sp[li];
        const float px = pt.x, py = pt.y;
        unsigned m = sinfo[li];
        int cc  = (m >> 10) & 31;
        int dxn = (int)((m >> 15) & 3) - 1;
        int dyn = (int)((m >> 17) & 3) - 1;
        bool vx = (m >> 19) & 1;
        bool vy = (m >> 20) & 1;

        int best = -1;
        SHADE_CELL(cc);
        if (vx) SHADE_CELL(cc + dxn * 5);
        if (vy) SHADE_CELL(cc + dyn);
        if (vx && vy) SHADE_CELL(cc + dxn * 5 + dyn);

        sbest[m & 1023] = (unsigned char)(best + 1);
    }
    __syncthreads();

    // ---- Phase 5: output in original order (dense 384B/warp stores) ----
#pragma unroll
    for (int k = 0; k < PPT; k++) {
        int li = k * TPB + tid;
        int gi = base + li;
        if (gi < n) {
            int cb = (int)sbest[li] * 3;
            out[gi * 3 + 0] = colors[cb + 0];
            out[gi * 3 + 1] = colors[cb + 1];
            out[gi * 3 + 2] = colors[cb + 2];
        }
    }
}

extern "C" void kernel_launch(void* const* d_in, const int* in_sizes, int n_in,
                              void* d_out, int out_size)
{
    // Identify inputs robustly: x has 2*N elements, p has 700
    int xi = 0, pi = 1;
    if (n_in >= 2 && in_sizes[0] < in_sizes[1]) { xi = 1; pi = 0; }
    const float* x = (const float*)d_in[xi];
    const float* p = (const float*)d_in[pi];
    float* out = (float*)d_out;

    int n = in_sizes[xi] / 2;
    int blocks = (n + TILE - 1) / TILE;
    vg_kernel<<<blocks, TPB>>>(x, p, out, n);
}